// round 10
// baseline (speedup 1.0000x reference)
#include <cuda_runtime.h>
#include <cuda_fp16.h>
#include <cstdint>
#include <cstddef>

#define BROWS 32768
#define DIN   256
#define UNITS 512

static constexpr float DT  = 1.0f / 6.0f;
static constexpr float DT2 = DT * 0.5f;
static constexpr float DT3 = DT / 3.0f;
static constexpr float DT6 = DT / 6.0f;

// ------------------------------------------------------------------ scratch
__device__ alignas(16) float  g_XKb[(size_t)BROWS * UNITS];
__device__ alignas(16) float  g_S  [(size_t)BROWS * UNITS];
__device__ alignas(16) __half g_H0h[(size_t)BROWS * UNITS];
__device__ alignas(16) __half g_H0l[(size_t)BROWS * UNITS];
__device__ alignas(16) __half g_HAh[(size_t)BROWS * UNITS];
__device__ alignas(16) __half g_HAl[(size_t)BROWS * UNITS];
__device__ alignas(16) __half g_HBh[(size_t)BROWS * UNITS];
__device__ alignas(16) __half g_HBl[(size_t)BROWS * UNITS];
__device__ alignas(16) __half g_Xh [(size_t)BROWS * DIN];
__device__ alignas(16) __half g_Xl [(size_t)BROWS * DIN];
__device__ alignas(16) __half g_Rth[UNITS * UNITS];
__device__ alignas(16) __half g_Kth[UNITS * DIN];

// ------------------------------------------------------------------ helpers
__device__ __forceinline__ uint32_t smem_u32(const void* p) {
    uint32_t a;
    asm("{ .reg .u64 t; cvta.to.shared.u64 t, %1; cvt.u32.u64 %0, t; }" : "=r"(a) : "l"(p));
    return a;
}

__device__ __forceinline__ void cp_async16(uint32_t saddr, const void* gaddr) {
    asm volatile("cp.async.cg.shared.global [%0], [%1], 16;" :: "r"(saddr), "l"(gaddr));
}
#define CP_COMMIT() asm volatile("cp.async.commit_group;" ::: "memory")
#define CP_WAIT(n)  asm volatile("cp.async.wait_group %0;" :: "n"(n) : "memory")

__device__ __forceinline__ void ldsm_x4(uint32_t addr, uint32_t& r0, uint32_t& r1,
                                        uint32_t& r2, uint32_t& r3) {
    asm volatile("ldmatrix.sync.aligned.m8n8.x4.shared.b16 {%0,%1,%2,%3}, [%4];"
                 : "=r"(r0), "=r"(r1), "=r"(r2), "=r"(r3) : "r"(addr));
}

__device__ __forceinline__ void mma16816(float* c, const uint32_t* a,
                                         uint32_t b0, uint32_t b1) {
    asm volatile("mma.sync.aligned.m16n8k16.row.col.f32.f16.f16.f32 "
                 "{%0,%1,%2,%3}, {%4,%5,%6,%7}, {%8,%9}, {%0,%1,%2,%3};"
                 : "+f"(c[0]), "+f"(c[1]), "+f"(c[2]), "+f"(c[3])
                 : "r"(a[0]), "r"(a[1]), "r"(a[2]), "r"(a[3]), "r"(b0), "r"(b1));
}

__device__ __forceinline__ float tanh_fast(float x) {
    const float e = __expf(2.0f * x);
    return 1.0f - 2.0f / (e + 1.0f);
}

__device__ __forceinline__ void hsplit2(__half* ph, __half* pl, float v0, float v1) {
    const __half h0 = __float2half(v0);
    const __half h1 = __float2half(v1);
    const __half l0 = __float2half(v0 - __half2float(h0));
    const __half l1 = __float2half(v1 - __half2float(h1));
    __half2 hh; hh.x = h0; hh.y = h1;
    __half2 ll; ll.x = l0; ll.y = l1;
    *reinterpret_cast<__half2*>(ph) = hh;
    *reinterpret_cast<__half2*>(pl) = ll;
}

// ------------------------------------------------------------------ smem map (dynamic)
// 3-deep chunk pipeline: 3 A bufs + 3 B bufs (16 KB each) + 512-float scale.
static constexpr uint32_t CH_BYTES = 128 * 128;           // 16 KB: 128 rows x 128B
static constexpr uint32_t OFF_A_BASE = 0;                 // A bufs 0..2
static constexpr uint32_t OFF_B_BASE = 3 * CH_BYTES;      // 49152: B bufs 0..2
static constexpr uint32_t OFF_SCL    = 6 * CH_BYTES;      // 98304: 512 floats
static constexpr uint32_t SMEM_BYTES = OFF_SCL + 2048 + 16;   // ~100.4 KB (2 CTAs/SM)

static constexpr int NTILES = (BROWS / 128) * (UNITS / 128);  // 1024

// ------------------------------------------------------------------ persistent stage kernel
// Each CTA loops over tiles j = bx, bx+G, ... with ONE continuous 3-buffer
// cp.async chunk stream crossing tile boundaries: the epilogue of tile j runs
// while chunks 0-1 of tile j+1 are in flight (epilogue <-> mainloop overlap).
// NPASS=2: [A_hi|A_lo]@[B_hi|B_hi] (x@K, once). NPASS=1: A_hi@B_hi (stages).
template <int MODE, int KSEG, int NPASS, bool LAST>
__global__ void __launch_bounds__(256, 2)
ctrnn_gemm(const float* __restrict__ sb, float* __restrict__ outp) {
    extern __shared__ char smem[];
    const uint32_t sbase = smem_u32(smem);
    const int tid  = threadIdx.x;
    const int lane = tid & 31;
    const int wid  = tid >> 5;
    const int warpM = (wid & 3) * 32;        // 4 warps along M
    const int warpN = (wid >> 2) * 64;       // 2 warps along N

    constexpr int CHPS = KSEG / 64;
    constexpr int NCH  = NPASS * CHPS;       // chunks per tile (== 8 in both configs)
    static_assert(NCH == 8, "chunk count must be 8");

    const __half *Ah, *Al, *Bh;
    if constexpr (MODE == 0)      { Ah = g_Xh;  Al = g_Xl;  Bh = g_Kth; }
    else if constexpr (MODE == 1) { Ah = g_H0h; Al = g_H0l; Bh = g_Rth; }
    else if constexpr (MODE == 2) { Ah = g_HAh; Al = g_HAl; Bh = g_Rth; }
    else if constexpr (MODE == 3) { Ah = g_HBh; Al = g_HBl; Bh = g_Rth; }
    else                          { Ah = g_HAh; Al = g_HAl; Bh = g_Rth; }

    __half *nxh = nullptr, *nxl = nullptr;
    if constexpr (MODE == 1)               { nxh = g_HAh; nxl = g_HAl; }
    else if constexpr (MODE == 2)          { nxh = g_HBh; nxl = g_HBl; }
    else if constexpr (MODE == 3)          { nxh = g_HAh; nxl = g_HAl; }
    else if constexpr (MODE == 4 && !LAST) { nxh = g_H0h; nxl = g_H0l; }

    // full 512-entry scale/bias table in SMEM (no per-tile reload)
    {
        float* s = reinterpret_cast<float*>(smem + OFF_SCL);
        s[tid] = sb[tid];
        s[tid + 256] = sb[tid + 256];
    }

    const __half* Aseg[2] = {Ah, (NPASS == 2) ? Al : Ah};

    const int G  = gridDim.x;
    const int bx = blockIdx.x;
    const int ntile = (bx < NTILES) ? ((NTILES - 1 - bx) / G + 1) : 0;
    const int Q = ntile * NCH;               // total chunks this CTA streams
    if (Q == 0) return;

    // slot mapping for cp.async: 1024 slots per 16KB chunk (128 rows x 8 col16)
    const int srow = tid >> 3;
    const int scol = tid & 7;

    auto issue = [&](int q) {
        const int k = q >> 3;                // tile ordinal
        const int c = q & 7;                 // chunk within tile
        const int j = bx + k * G;            // global tile id
        const int rowBase = (j >> 2) * 128;
        const int nBase   = (j & 3) * 128;
        const int seg = c / CHPS;
        const int kof = (c % CHPS) * 64;
        const __half* As = Aseg[seg];
        const int buf = q % 3;
        const uint32_t aOff = OFF_A_BASE + (uint32_t)buf * CH_BYTES;
        const uint32_t bOff = OFF_B_BASE + (uint32_t)buf * CH_BYTES;
#pragma unroll
        for (int i = 0; i < 4; ++i) {
            const int r = srow + i * 32;
            uint32_t off = (uint32_t)(r * 128 + ((scol ^ (r & 7)) << 4));
            cp_async16(sbase + aOff + off,
                       As + (size_t)(rowBase + r) * KSEG + kof + scol * 8);
        }
#pragma unroll
        for (int i = 0; i < 4; ++i) {
            const int r = srow + i * 32;
            uint32_t off = (uint32_t)(r * 128 + ((scol ^ (r & 7)) << 4));
            cp_async16(sbase + bOff + off,
                       Bh + (size_t)(nBase + r) * KSEG + kof + scol * 8);
        }
        CP_COMMIT();
    };

    float acc[2][8][4];
#pragma unroll
    for (int mf = 0; mf < 2; ++mf)
#pragma unroll
        for (int nf = 0; nf < 8; ++nf)
#pragma unroll
            for (int i = 0; i < 4; ++i) acc[mf][nf][i] = 0.0f;

    const float* scl = reinterpret_cast<const float*>(smem + OFF_SCL);

    issue(0);
    issue(1);

    for (int q = 0; q < Q; ++q) {
        if (q + 2 < Q) { CP_WAIT(1); } else { CP_WAIT(0); }
        __syncthreads();
        if (q + 2 < Q) issue(q + 2);

        // ---- MMA on buffer q%3 ----
        {
            const int buf = q % 3;
            const uint32_t aBase = sbase + OFF_A_BASE + (uint32_t)buf * CH_BYTES;
            const uint32_t bBase = sbase + OFF_B_BASE + (uint32_t)buf * CH_BYTES;
#pragma unroll
            for (int p = 0; p < 4; ++p) {
                uint32_t a[2][4];
#pragma unroll
                for (int mf = 0; mf < 2; ++mf) {
                    const int row = warpM + mf * 16 + ((lane >> 3) & 1) * 8 + (lane & 7);
                    const int c16 = p * 2 + (lane >> 4);
                    const uint32_t addr = aBase + row * 128 + (((c16 ^ (row & 7)) & 7) << 4);
                    ldsm_x4(addr, a[mf][0], a[mf][1], a[mf][2], a[mf][3]);
                }
#pragma unroll
                for (int g = 0; g < 4; ++g) {
                    uint32_t b0, b1, b2, b3;
                    const int row = warpN + g * 16 + ((lane >> 3) & 1) * 8 + (lane & 7);
                    const int c16 = p * 2 + (lane >> 4);
                    const uint32_t addr = bBase + row * 128 + (((c16 ^ (row & 7)) & 7) << 4);
                    ldsm_x4(addr, b0, b1, b2, b3);
#pragma unroll
                    for (int mf = 0; mf < 2; ++mf) {
                        mma16816(acc[mf][2 * g],     a[mf], b0, b2);
                        mma16816(acc[mf][2 * g + 1], a[mf], b1, b3);
                    }
                }
            }
        }

        // ---- tile finished -> RK4 epilogue (overlaps next tile's in-flight loads) ----
        if ((q & 7) == 7) {
            const int j = bx + (q >> 3) * G;
            const int rowBase = (j >> 2) * 128;
            const int nBase   = (j & 3) * 128;
#pragma unroll
            for (int mf = 0; mf < 2; ++mf) {
#pragma unroll
                for (int nf = 0; nf < 8; ++nf) {
#pragma unroll
                    for (int half_ = 0; half_ < 2; ++half_) {
                        const int row = rowBase + warpM + mf * 16 + (lane >> 2) + half_ * 8;
                        const int col = nBase + warpN + nf * 8 + (lane & 3) * 2;
                        const float c0 = acc[mf][nf][half_ * 2 + 0];
                        const float c1 = acc[mf][nf][half_ * 2 + 1];
                        const size_t eb = (size_t)row * UNITS + col;

                        if constexpr (MODE == 0) {
                            float2 o;
                            o.x = c0 + scl[col];
                            o.y = c1 + scl[col + 1];
                            *reinterpret_cast<float2*>(g_XKb + eb) = o;
                        } else {
                            const float2 xk = *reinterpret_cast<const float2*>(g_XKb + eb);
                            const __half2 ah = *reinterpret_cast<const __half2*>(Ah + eb);
                            const __half2 al = *reinterpret_cast<const __half2*>(Al + eb);
                            const float hs0 = __half2float(ah.x) + __half2float(al.x);
                            const float hs1 = __half2float(ah.y) + __half2float(al.y);
                            const float k0 = scl[col]     * tanh_fast(c0 + xk.x) - hs0;
                            const float k1 = scl[col + 1] * tanh_fast(c1 + xk.y) - hs1;

                            if constexpr (MODE == 1) {
                                hsplit2(nxh + eb, nxl + eb, hs0 + DT2 * k0, hs1 + DT2 * k1);
                                float2 sv; sv.x = hs0 + DT6 * k0; sv.y = hs1 + DT6 * k1;
                                *reinterpret_cast<float2*>(g_S + eb) = sv;
                            } else if constexpr (MODE == 2 || MODE == 3) {
                                const __half2 h0a = *reinterpret_cast<const __half2*>(g_H0h + eb);
                                const __half2 h0b = *reinterpret_cast<const __half2*>(g_H0l + eb);
                                const float h00 = __half2float(h0a.x) + __half2float(h0b.x);
                                const float h01 = __half2float(h0a.y) + __half2float(h0b.y);
                                const float2 s = *reinterpret_cast<const float2*>(g_S + eb);
                                constexpr float HC = (MODE == 2) ? DT2 : DT;
                                hsplit2(nxh + eb, nxl + eb, h00 + HC * k0, h01 + HC * k1);
                                float2 sn; sn.x = s.x + DT3 * k0; sn.y = s.y + DT3 * k1;
                                *reinterpret_cast<float2*>(g_S + eb) = sn;
                            } else {  // MODE 4
                                const float2 s = *reinterpret_cast<const float2*>(g_S + eb);
                                const float f0 = s.x + DT6 * k0;
                                const float f1 = s.y + DT6 * k1;
                                if constexpr (LAST) {
                                    float2 o; o.x = f0; o.y = f1;
                                    *reinterpret_cast<float2*>(outp + eb) = o;
                                } else {
                                    hsplit2(nxh + eb, nxl + eb, f0, f1);
                                }
                            }
                        }
                    }
                }
            }
            // reset accumulators for the next tile
#pragma unroll
            for (int mf = 0; mf < 2; ++mf)
#pragma unroll
                for (int nf = 0; nf < 8; ++nf)
#pragma unroll
                    for (int i = 0; i < 4; ++i) acc[mf][nf][i] = 0.0f;
        }
    }
}

// ------------------------------------------------------------------ prep kernels
__global__ void split_kernel(const float* __restrict__ src,
                             __half* __restrict__ hi, __half* __restrict__ lo, int n4) {
    const int i = blockIdx.x * blockDim.x + threadIdx.x;
    if (i >= n4) return;
    const float4 v = reinterpret_cast<const float4*>(src)[i];
    hsplit2(hi + (size_t)i * 4,     lo + (size_t)i * 4,     v.x, v.y);
    hsplit2(hi + (size_t)i * 4 + 2, lo + (size_t)i * 4 + 2, v.z, v.w);
}

__global__ void trans_kernel(const float* __restrict__ W,
                             __half* __restrict__ Th, int K, int N) {
    const int idx = blockIdx.x * blockDim.x + threadIdx.x;
    if (idx >= K * N) return;
    const int k = idx / N, n = idx % N;
    Th[(size_t)n * K + k] = __float2half(W[idx]);
}

// ------------------------------------------------------------------ launch
extern "C" void kernel_launch(void* const* d_in, const int* in_sizes, int n_in,
                              void* d_out, int out_size) {
    const float* x     = (const float*)d_in[0];
    const float* h     = (const float*)d_in[1];
    const float* Km    = (const float*)d_in[2];
    const float* Rm    = (const float*)d_in[3];
    const float* bias  = (const float*)d_in[4];
    const float* scale = (const float*)d_in[5];
    float* out = (float*)d_out;

    cudaFuncSetAttribute(ctrnn_gemm<0, 256, 2, false>, cudaFuncAttributeMaxDynamicSharedMemorySize, SMEM_BYTES);
    cudaFuncSetAttribute(ctrnn_gemm<1, 512, 1, false>, cudaFuncAttributeMaxDynamicSharedMemorySize, SMEM_BYTES);
    cudaFuncSetAttribute(ctrnn_gemm<2, 512, 1, false>, cudaFuncAttributeMaxDynamicSharedMemorySize, SMEM_BYTES);
    cudaFuncSetAttribute(ctrnn_gemm<3, 512, 1, false>, cudaFuncAttributeMaxDynamicSharedMemorySize, SMEM_BYTES);
    cudaFuncSetAttribute(ctrnn_gemm<4, 512, 1, false>, cudaFuncAttributeMaxDynamicSharedMemorySize, SMEM_BYTES);
    cudaFuncSetAttribute(ctrnn_gemm<4, 512, 1, true>,  cudaFuncAttributeMaxDynamicSharedMemorySize, SMEM_BYTES);

    __half *h0h, *h0l, *xh, *xl, *rth, *kth;
    cudaGetSymbolAddress((void**)&h0h, g_H0h);
    cudaGetSymbolAddress((void**)&h0l, g_H0l);
    cudaGetSymbolAddress((void**)&xh,  g_Xh);
    cudaGetSymbolAddress((void**)&xl,  g_Xl);
    cudaGetSymbolAddress((void**)&rth, g_Rth);
    cudaGetSymbolAddress((void**)&kth, g_Kth);

    split_kernel<<<(BROWS * UNITS / 4) / 256, 256>>>(h, h0h, h0l, BROWS * UNITS / 4);
    split_kernel<<<(BROWS * DIN / 4) / 256, 256>>>(x, xh, xl, BROWS * DIN / 4);
    trans_kernel<<<(UNITS * UNITS) / 256, 256>>>(Rm, rth, UNITS, UNITS);
    trans_kernel<<<(DIN * UNITS) / 256, 256>>>(Km, kth, DIN, UNITS);

    int smc = 148;
    cudaDeviceGetAttribute(&smc, cudaDevAttrMultiProcessorCount, 0);
    const dim3 gg(2 * smc);    // exactly fills the chip at 2 CTAs/SM; no sync -> any grid safe

    ctrnn_gemm<0, 256, 2, false><<<gg, 256, SMEM_BYTES>>>(bias, nullptr);

    for (int u = 0; u < 6; ++u) {
        ctrnn_gemm<1, 512, 1, false><<<gg, 256, SMEM_BYTES>>>(scale, nullptr);
        ctrnn_gemm<2, 512, 1, false><<<gg, 256, SMEM_BYTES>>>(scale, nullptr);
        ctrnn_gemm<3, 512, 1, false><<<gg, 256, SMEM_BYTES>>>(scale, nullptr);
        if (u == 5) ctrnn_gemm<4, 512, 1, true><<<gg, 256, SMEM_BYTES>>>(scale, out);
        else        ctrnn_gemm<4, 512, 1, false><<<gg, 256, SMEM_BYTES>>>(scale, nullptr);
    }
}

// round 11
// speedup vs baseline: 1.1839x; 1.1839x over previous
#include <cuda_runtime.h>
#include <cuda_fp16.h>
#include <cstdint>
#include <cstddef>

#define BROWS 32768
#define DIN   256
#define UNITS 512

static constexpr float DT  = 1.0f / 6.0f;
static constexpr float DT2 = DT * 0.5f;
static constexpr float DT3 = DT / 3.0f;
static constexpr float DT6 = DT / 6.0f;

// ------------------------------------------------------------------ scratch
__device__ alignas(16) float  g_XKb[(size_t)BROWS * UNITS];
__device__ alignas(16) float  g_S  [(size_t)BROWS * UNITS];
__device__ alignas(16) __half g_H0h[(size_t)BROWS * UNITS];
__device__ alignas(16) __half g_H0l[(size_t)BROWS * UNITS];
__device__ alignas(16) __half g_HAh[(size_t)BROWS * UNITS];
__device__ alignas(16) __half g_HAl[(size_t)BROWS * UNITS];
__device__ alignas(16) __half g_HBh[(size_t)BROWS * UNITS];
__device__ alignas(16) __half g_HBl[(size_t)BROWS * UNITS];
__device__ alignas(16) __half g_Xh [(size_t)BROWS * DIN];
__device__ alignas(16) __half g_Xl [(size_t)BROWS * DIN];
__device__ alignas(16) __half g_Rth[UNITS * UNITS];
__device__ alignas(16) __half g_Kth[UNITS * DIN];

// ------------------------------------------------------------------ helpers
__device__ __forceinline__ uint32_t smem_u32(const void* p) {
    uint32_t a;
    asm("{ .reg .u64 t; cvta.to.shared.u64 t, %1; cvt.u32.u64 %0, t; }" : "=r"(a) : "l"(p));
    return a;
}

__device__ __forceinline__ void cp_async16(uint32_t saddr, const void* gaddr) {
    asm volatile("cp.async.cg.shared.global [%0], [%1], 16;" :: "r"(saddr), "l"(gaddr));
}
#define CP_COMMIT() asm volatile("cp.async.commit_group;" ::: "memory")
#define CP_WAIT(n)  asm volatile("cp.async.wait_group %0;" :: "n"(n) : "memory")

__device__ __forceinline__ void pf_l2(const void* p) {
    asm volatile("prefetch.global.L2 [%0];" :: "l"(p));
}

__device__ __forceinline__ void ldsm_x4(uint32_t addr, uint32_t& r0, uint32_t& r1,
                                        uint32_t& r2, uint32_t& r3) {
    asm volatile("ldmatrix.sync.aligned.m8n8.x4.shared.b16 {%0,%1,%2,%3}, [%4];"
                 : "=r"(r0), "=r"(r1), "=r"(r2), "=r"(r3) : "r"(addr));
}

__device__ __forceinline__ void mma16816(float* c, const uint32_t* a,
                                         uint32_t b0, uint32_t b1) {
    asm volatile("mma.sync.aligned.m16n8k16.row.col.f32.f16.f16.f32 "
                 "{%0,%1,%2,%3}, {%4,%5,%6,%7}, {%8,%9}, {%0,%1,%2,%3};"
                 : "+f"(c[0]), "+f"(c[1]), "+f"(c[2]), "+f"(c[3])
                 : "r"(a[0]), "r"(a[1]), "r"(a[2]), "r"(a[3]), "r"(b0), "r"(b1));
}

__device__ __forceinline__ float tanh_fast(float x) {
    const float e = __expf(2.0f * x);
    return 1.0f - 2.0f / (e + 1.0f);
}

__device__ __forceinline__ void hsplit2(__half* ph, __half* pl, float v0, float v1) {
    const __half h0 = __float2half(v0);
    const __half h1 = __float2half(v1);
    const __half l0 = __float2half(v0 - __half2float(h0));
    const __half l1 = __float2half(v1 - __half2float(h1));
    __half2 hh; hh.x = h0; hh.y = h1;
    __half2 ll; ll.x = l0; ll.y = l1;
    *reinterpret_cast<__half2*>(ph) = hh;
    *reinterpret_cast<__half2*>(pl) = ll;
}

// ------------------------------------------------------------------ smem map (dynamic)
static constexpr uint32_t TILE_BYTES = 128 * 128;         // 128 rows x 128B (64 halfs)
static constexpr uint32_t OFF_A0  = 0;
static constexpr uint32_t OFF_A1  = OFF_A0 + TILE_BYTES;  // 16384
static constexpr uint32_t OFF_B0  = OFF_A1 + TILE_BYTES;  // 32768
static constexpr uint32_t OFF_B1  = OFF_B0 + TILE_BYTES;  // 49152
static constexpr uint32_t OFF_SCL = OFF_B1 + TILE_BYTES;  // 65536
static constexpr uint32_t SMEM_BYTES = OFF_SCL + 512 + 16;

// ------------------------------------------------------------------ main GEMM + RK4 epilogue
// NPASS=2: [A_hi | A_lo] @ [B_hi | B_hi]  — used for x@K (once)
// NPASS=1: A_hi @ B_hi                    — stage GEMMs (~1.8e-4 total err)
// LATE L2 prefetch (chunks 5-7, ~2-6us before use) of cold epilogue operands:
// in-flight footprint stays ~30MB chip-wide (fits L2), unlike the early
// variant which thrashed at ~86MB.
template <int MODE, int KSEG, int NPASS, bool LAST>
__global__ void __launch_bounds__(256, 2)
ctrnn_gemm(const float* __restrict__ sb, float* __restrict__ outp) {
    extern __shared__ char smem[];
    const uint32_t sbase = smem_u32(smem);
    const int tid  = threadIdx.x;
    const int lane = tid & 31;
    const int wid  = tid >> 5;
    const int warpM = (wid & 3) * 32;        // 4 warps along M
    const int warpN = (wid >> 2) * 64;       // 2 warps along N
    const int rowBase = blockIdx.y * 128;
    const int nBase   = blockIdx.x * 128;

    constexpr int CHPS = KSEG / 64;
    constexpr int NCH  = NPASS * CHPS;

    const __half *Ah, *Al, *Bh;
    if constexpr (MODE == 0)      { Ah = g_Xh;  Al = g_Xl;  Bh = g_Kth; }
    else if constexpr (MODE == 1) { Ah = g_H0h; Al = g_H0l; Bh = g_Rth; }
    else if constexpr (MODE == 2) { Ah = g_HAh; Al = g_HAl; Bh = g_Rth; }
    else if constexpr (MODE == 3) { Ah = g_HBh; Al = g_HBl; Bh = g_Rth; }
    else                          { Ah = g_HAh; Al = g_HAl; Bh = g_Rth; }

    __half *nxh = nullptr, *nxl = nullptr;
    if constexpr (MODE == 1)               { nxh = g_HAh; nxl = g_HAl; }
    else if constexpr (MODE == 2)          { nxh = g_HBh; nxl = g_HBl; }
    else if constexpr (MODE == 3)          { nxh = g_HAh; nxl = g_HAl; }
    else if constexpr (MODE == 4 && !LAST) { nxh = g_H0h; nxl = g_H0l; }

    if (tid < 128)
        reinterpret_cast<float*>(smem + OFF_SCL)[tid] = sb[nBase + tid];

    const __half* Aseg[2] = {Ah, (NPASS == 2) ? Al : Ah};

    // slot mapping for cp.async: 1024 slots per tile (128 rows x 8 col16)
    const int srow = tid >> 3;
    const int scol = tid & 7;

    auto load_chunk = [&](int c, int buf) {
        const int seg = c / CHPS;
        const int kof = (c % CHPS) * 64;
        const __half* As = Aseg[seg];
        const __half* Bs = Bh;
        const uint32_t aOff = buf ? OFF_A1 : OFF_A0;
        const uint32_t bOff = buf ? OFF_B1 : OFF_B0;
#pragma unroll
        for (int i = 0; i < 4; ++i) {
            const int r = srow + i * 32;
            uint32_t off = (uint32_t)(r * 128 + ((scol ^ (r & 7)) << 4));
            cp_async16(sbase + aOff + off,
                       As + (size_t)(rowBase + r) * KSEG + kof + scol * 8);
        }
#pragma unroll
        for (int i = 0; i < 4; ++i) {
            const int r = srow + i * 32;
            uint32_t off = (uint32_t)(r * 128 + ((scol ^ (r & 7)) << 4));
            cp_async16(sbase + bOff + off,
                       Bs + (size_t)(nBase + r) * KSEG + kof + scol * 8);
        }
        CP_COMMIT();
    };

    // L2 prefetch helpers for this CTA's 128x128 epilogue tile.
    auto pf_f32 = [&](const float* base) {
        const int L0 = tid;            // 512 lines of 128B, 2/thread
        pf_l2(base + (size_t)(rowBase + (L0 >> 2)) * UNITS + nBase + (L0 & 3) * 32);
        const int L1 = tid + 256;
        pf_l2(base + (size_t)(rowBase + (L1 >> 2)) * UNITS + nBase + (L1 & 3) * 32);
    };
    auto pf_f16 = [&](const __half* base) {
        const int L = tid;             // 256 lines, 1/thread
        pf_l2(base + (size_t)(rowBase + (L >> 1)) * UNITS + nBase + (L & 1) * 64);
    };

    float acc[2][8][4];
#pragma unroll
    for (int mf = 0; mf < 2; ++mf)
#pragma unroll
        for (int nf = 0; nf < 8; ++nf)
#pragma unroll
            for (int i = 0; i < 4; ++i) acc[mf][nf][i] = 0.0f;

    // 2-stage pipeline: one barrier per chunk; L(c+1) overlaps MMA(c).
    load_chunk(0, 0);

    for (int c = 0; c < NCH; ++c) {
        CP_WAIT(0);
        __syncthreads();
        if (c + 1 < NCH) load_chunk(c + 1, (c + 1) & 1);

        // LATE prefetch of epilogue operands (close to use; avoids L2 thrash)
        if constexpr (MODE != 0) {
            if (c == NCH - 3) {
                pf_f32(g_XKb);
                pf_f16(Al);
            } else if (c == NCH - 2) {
                if constexpr (MODE >= 2) pf_f32(g_S);
                if constexpr (MODE == 2 || MODE == 3) { pf_f16(g_H0h); pf_f16(g_H0l); }
            }
        }

        const uint32_t aBase = sbase + ((c & 1) ? OFF_A1 : OFF_A0);
        const uint32_t bBase = sbase + ((c & 1) ? OFF_B1 : OFF_B0);
#pragma unroll
        for (int q = 0; q < 4; ++q) {
            uint32_t a[2][4];
#pragma unroll
            for (int mf = 0; mf < 2; ++mf) {
                const int row = warpM + mf * 16 + ((lane >> 3) & 1) * 8 + (lane & 7);
                const int c16 = q * 2 + (lane >> 4);
                const uint32_t addr = aBase + row * 128 + (((c16 ^ (row & 7)) & 7) << 4);
                ldsm_x4(addr, a[mf][0], a[mf][1], a[mf][2], a[mf][3]);
            }
#pragma unroll
            for (int g = 0; g < 4; ++g) {
                uint32_t b0, b1, b2, b3;
                const int row = warpN + g * 16 + ((lane >> 3) & 1) * 8 + (lane & 7);
                const int c16 = q * 2 + (lane >> 4);
                const uint32_t addr = bBase + row * 128 + (((c16 ^ (row & 7)) & 7) << 4);
                ldsm_x4(addr, b0, b1, b2, b3);
#pragma unroll
                for (int mf = 0; mf < 2; ++mf) {
                    mma16816(acc[mf][2 * g],     a[mf], b0, b2);
                    mma16816(acc[mf][2 * g + 1], a[mf], b1, b3);
                }
            }
        }
    }

    // ---------------- RK4 epilogue ----------------
    const float* scl = reinterpret_cast<const float*>(smem + OFF_SCL);

#pragma unroll
    for (int mf = 0; mf < 2; ++mf) {
#pragma unroll
        for (int nf = 0; nf < 8; ++nf) {
#pragma unroll
            for (int half_ = 0; half_ < 2; ++half_) {
                const int row = rowBase + warpM + mf * 16 + (lane >> 2) + half_ * 8;
                const int lc  = warpN + nf * 8 + (lane & 3) * 2;   // local col 0..127
                const int col = nBase + lc;
                const float c0 = acc[mf][nf][half_ * 2 + 0];
                const float c1 = acc[mf][nf][half_ * 2 + 1];
                const size_t eb = (size_t)row * UNITS + col;

                if constexpr (MODE == 0) {
                    float2 o;
                    o.x = c0 + scl[lc];
                    o.y = c1 + scl[lc + 1];
                    *reinterpret_cast<float2*>(g_XKb + eb) = o;
                } else {
                    const float2 xk = *reinterpret_cast<const float2*>(g_XKb + eb);
                    const __half2 ah = *reinterpret_cast<const __half2*>(Ah + eb);
                    const __half2 al = *reinterpret_cast<const __half2*>(Al + eb);
                    const float hs0 = __half2float(ah.x) + __half2float(al.x);
                    const float hs1 = __half2float(ah.y) + __half2float(al.y);
                    const float k0 = scl[lc]     * tanh_fast(c0 + xk.x) - hs0;
                    const float k1 = scl[lc + 1] * tanh_fast(c1 + xk.y) - hs1;

                    if constexpr (MODE == 1) {
                        hsplit2(nxh + eb, nxl + eb, hs0 + DT2 * k0, hs1 + DT2 * k1);
                        float2 sv; sv.x = hs0 + DT6 * k0; sv.y = hs1 + DT6 * k1;
                        *reinterpret_cast<float2*>(g_S + eb) = sv;
                    } else if constexpr (MODE == 2 || MODE == 3) {
                        const __half2 h0a = *reinterpret_cast<const __half2*>(g_H0h + eb);
                        const __half2 h0b = *reinterpret_cast<const __half2*>(g_H0l + eb);
                        const float h00 = __half2float(h0a.x) + __half2float(h0b.x);
                        const float h01 = __half2float(h0a.y) + __half2float(h0b.y);
                        const float2 s = *reinterpret_cast<const float2*>(g_S + eb);
                        constexpr float HC = (MODE == 2) ? DT2 : DT;
                        hsplit2(nxh + eb, nxl + eb, h00 + HC * k0, h01 + HC * k1);
                        float2 sn; sn.x = s.x + DT3 * k0; sn.y = s.y + DT3 * k1;
                        *reinterpret_cast<float2*>(g_S + eb) = sn;
                    } else {  // MODE 4
                        const float2 s = *reinterpret_cast<const float2*>(g_S + eb);
                        const float f0 = s.x + DT6 * k0;
                        const float f1 = s.y + DT6 * k1;
                        if constexpr (LAST) {
                            float2 o; o.x = f0; o.y = f1;
                            *reinterpret_cast<float2*>(outp + eb) = o;
                        } else {
                            hsplit2(nxh + eb, nxl + eb, f0, f1);
                        }
                    }
                }
            }
        }
    }
}

// ------------------------------------------------------------------ fused prep kernel
// One launch does all conversions so the stage GEMMs start at launch index 2
// (and ncu -s 5 lands on a stage kernel, not prep).
__global__ void prep_all_kernel(const float* __restrict__ h, const float* __restrict__ x,
                                const float* __restrict__ Rm, const float* __restrict__ Km) {
    const int i = blockIdx.x * blockDim.x + threadIdx.x;

    // task A: split hidden state (BROWS*UNITS/4 float4 groups)
    {
        const int nA = BROWS * UNITS / 4;
        if (i < nA) {
            const float4 v = reinterpret_cast<const float4*>(h)[i];
            hsplit2(g_H0h + (size_t)i * 4,     g_H0l + (size_t)i * 4,     v.x, v.y);
            hsplit2(g_H0h + (size_t)i * 4 + 2, g_H0l + (size_t)i * 4 + 2, v.z, v.w);
        }
    }
    // task B: split x
    {
        const int nB = BROWS * DIN / 4;
        if (i < nB) {
            const float4 v = reinterpret_cast<const float4*>(x)[i];
            hsplit2(g_Xh + (size_t)i * 4,     g_Xl + (size_t)i * 4,     v.x, v.y);
            hsplit2(g_Xh + (size_t)i * 4 + 2, g_Xl + (size_t)i * 4 + 2, v.z, v.w);
        }
    }
    // task C: transpose R -> Rth (K-major for MMA B operand)
    {
        const int nC = UNITS * UNITS;
        if (i < nC) {
            const int k = i / UNITS, n = i % UNITS;
            g_Rth[(size_t)n * UNITS + k] = __float2half(Rm[i]);
        }
    }
    // task D: transpose K -> Kth
    {
        const int nD = DIN * UNITS;
        if (i < nD) {
            const int k = i / UNITS, n = i % UNITS;
            g_Kth[(size_t)n * DIN + k] = __float2half(Km[i]);
        }
    }
}

// ------------------------------------------------------------------ launch
extern "C" void kernel_launch(void* const* d_in, const int* in_sizes, int n_in,
                              void* d_out, int out_size) {
    const float* x     = (const float*)d_in[0];
    const float* h     = (const float*)d_in[1];
    const float* Km    = (const float*)d_in[2];
    const float* Rm    = (const float*)d_in[3];
    const float* bias  = (const float*)d_in[4];
    const float* scale = (const float*)d_in[5];
    float* out = (float*)d_out;

    cudaFuncSetAttribute(ctrnn_gemm<0, 256, 2, false>, cudaFuncAttributeMaxDynamicSharedMemorySize, SMEM_BYTES);
    cudaFuncSetAttribute(ctrnn_gemm<1, 512, 1, false>, cudaFuncAttributeMaxDynamicSharedMemorySize, SMEM_BYTES);
    cudaFuncSetAttribute(ctrnn_gemm<2, 512, 1, false>, cudaFuncAttributeMaxDynamicSharedMemorySize, SMEM_BYTES);
    cudaFuncSetAttribute(ctrnn_gemm<3, 512, 1, false>, cudaFuncAttributeMaxDynamicSharedMemorySize, SMEM_BYTES);
    cudaFuncSetAttribute(ctrnn_gemm<4, 512, 1, false>, cudaFuncAttributeMaxDynamicSharedMemorySize, SMEM_BYTES);
    cudaFuncSetAttribute(ctrnn_gemm<4, 512, 1, true>,  cudaFuncAttributeMaxDynamicSharedMemorySize, SMEM_BYTES);

    // one prep launch (largest task: BROWS*UNITS/4 = 4.19M threads)
    const int nPrep = BROWS * UNITS / 4;
    prep_all_kernel<<<(nPrep + 255) / 256, 256>>>(h, x, Rm, Km);

    // N-block fastest (x), M-block slow (y): CTAs sharing A-rows are L2-concurrent.
    const dim3 gg(UNITS / 128, BROWS / 128);
    ctrnn_gemm<0, 256, 2, false><<<gg, 256, SMEM_BYTES>>>(bias, nullptr);

    for (int u = 0; u < 6; ++u) {
        ctrnn_gemm<1, 512, 1, false><<<gg, 256, SMEM_BYTES>>>(scale, nullptr);
        ctrnn_gemm<2, 512, 1, false><<<gg, 256, SMEM_BYTES>>>(scale, nullptr);
        ctrnn_gemm<3, 512, 1, false><<<gg, 256, SMEM_BYTES>>>(scale, nullptr);
        if (u == 5) ctrnn_gemm<4, 512, 1, true><<<gg, 256, SMEM_BYTES>>>(scale, out);
        else        ctrnn_gemm<4, 512, 1, false><<<gg, 256, SMEM_BYTES>>>(scale, nullptr);
    }
}